// round 14
// baseline (speedup 1.0000x reference)
#include <cuda_runtime.h>
#include <cuda_bf16.h>
#include <cstdint>

#define NTHR 256
#define TOKB 128
#define EXPN 64
#define CDIM 2048
#define BT   16384
#define BDIM 4
#define TOPK 6
#define KSTEP_U32 512            // u32 per kstep packed W (4 jp * 32 lanes * 4)
#define CHUNK_U32 (4*KSTEP_U32)  // 2048 u32 = 8KB (4 ksteps)
#define LSTR 66
#define GUARD 0.012f
#define SMEM_BYTES (4*CHUNK_U32*4 + TOKB*LSTR*4)   // 32768 + 33792 = 66560

// refine smem layout (floats)
#define RWS  0
#define RXS  (64*130)
#define RLG  (64*130 + 32*130)
#define REFINE_SMEM ((64*130 + 32*130 + 320) * 4)   // 51200 B

__device__ float g_sums[BDIM * EXPN];
__device__ float g_cnts[BDIM * EXPN];
__device__ int   g_fullcnt;
__device__ int   g_ffull[BT];
__device__ uint4 g_info[BT];               // {ids0, ids1, S_rest, m}
__device__ uint32_t wsg[128 * KSTEP_U32];  // 256 KB packed 1-plane bf16 W fragments

static __device__ __forceinline__ void cp16(void* smem_ptr, const void* gptr) {
    unsigned saddr = (unsigned)__cvta_generic_to_shared(smem_ptr);
    asm volatile("cp.async.cg.shared.global [%0], [%1], 16;\n" :: "r"(saddr), "l"(gptr));
}
#define CP_COMMIT() asm volatile("cp.async.commit_group;\n" ::: "memory")

static __device__ __forceinline__ void mma16816(float* c, const uint32_t* a,
                                                uint32_t b0, uint32_t b1) {
    asm volatile("mma.sync.aligned.m16n8k16.row.col.f32.bf16.bf16.f32 "
        "{%0,%1,%2,%3}, {%4,%5,%6,%7}, {%8,%9}, {%0,%1,%2,%3};"
        : "+f"(c[0]), "+f"(c[1]), "+f"(c[2]), "+f"(c[3])
        : "r"(a[0]), "r"(a[1]), "r"(a[2]), "r"(a[3]), "r"(b0), "r"(b1));
}

static __device__ __forceinline__ uint32_t cvt2(float f0, float f1) {
    __nv_bfloat162 b = __floats2bfloat162_rn(f0, f1);
    return *(uint32_t*)&b;
}

// ---------------- W prep: single bf16 plane, B-fragment lane order ----------------
__global__ void prep_kernel(const float* __restrict__ w) {
    int id = blockIdx.x * 256 + threadIdx.x;   // 32768 = 128 ksteps * 8 ntiles * 32 lanes
    if (id < BDIM * EXPN) { g_sums[id] = 0.f; g_cnts[id] = 0.f; }
    if (id == 0) g_fullcnt = 0;
    int s = id >> 8;
    int j = (id >> 5) & 7;
    int l = id & 31;
    int n  = 8 * j + (l >> 2);
    int k0 = s * 16 + (l & 3) * 2;
    const float* wr = w + (size_t)n * CDIM + k0;
    float2 flo = *(const float2*)wr;
    float2 fhi = *(const float2*)(wr + 8);
    uint32_t b0 = cvt2(flo.x, flo.y);
    uint32_t b1 = cvt2(fhi.x, fhi.y);
    uint32_t base = (uint32_t)(((s * 4 + (j >> 1)) * 32 + l) * 4 + (j & 1) * 2);
    wsg[base]     = b0;
    wsg[base + 1] = b1;
}

// ---------------- gate: 1-term bf16 HMMA, emits candidates only ----------------
__global__ void __launch_bounds__(NTHR, 1)
gate_kernel(const float* __restrict__ x) {
    extern __shared__ char smem[];
    uint32_t* wbuf = (uint32_t*)smem;                 // 4 x 8KB chunk buffers
    float* lsm = (float*)(smem + 4 * CHUNK_U32 * 4);
    __shared__ float s_sums[EXPN];

    const int tid  = threadIdx.x;
    const int wid  = tid >> 5;
    const int lane = tid & 31;
    const int blk  = blockIdx.x;
    const int wg   = wid & 3;    // token group (32 tokens)
    const int kh   = wid >> 2;   // k-half

    if (tid < EXPN) s_sums[tid] = 0.f;

    const int r  = lane >> 2;
    const int c0 = (lane & 3) * 2;
    const float* xr0 = x + ((size_t)blk * TOKB + wg * 32 + r) * CDIM + kh * 1024;
    const float* xr1 = xr0 + (size_t)16 * CDIM;

    float cacc[2][8][4];
#pragma unroll
    for (int m = 0; m < 2; m++)
#pragma unroll
        for (int j = 0; j < 8; j++)
#pragma unroll
            for (int q = 0; q < 4; q++) cacc[m][j][q] = 0.f;

    auto load2 = [&](int c) {
        int par = c & 1;
        const uint4* s0 = (const uint4*)(wsg + (size_t)c * CHUNK_U32);
        const uint4* s1 = (const uint4*)(wsg + (size_t)(16 + c) * CHUNK_U32);
        uint4* d0 = (uint4*)(wbuf + par * CHUNK_U32);
        uint4* d1 = (uint4*)(wbuf + (2 + par) * CHUNK_U32);
#pragma unroll
        for (int i = 0; i < 2; i++) cp16(d0 + tid + i * NTHR, s0 + tid + i * NTHR);
#pragma unroll
        for (int i = 0; i < 2; i++) cp16(d1 + tid + i * NTHR, s1 + tid + i * NTHR);
        CP_COMMIT();
    };

    load2(0);
    load2(1);

    for (int c = 0; c < 16; c++) {
        if (c + 1 < 16) asm volatile("cp.async.wait_group 1;\n" ::: "memory");
        else            asm volatile("cp.async.wait_group 0;\n" ::: "memory");
        __syncthreads();

        const uint32_t* wb = wbuf + (kh * 2 + (c & 1)) * CHUNK_U32;

#pragma unroll
        for (int kc = 0; kc < 4; kc++) {
            const int koff = (c * 4 + kc) * 16 + c0;
            uint32_t A[2][4];
#pragma unroll
            for (int m = 0; m < 2; m++) {
                const float* xp = (m == 0 ? xr0 : xr1) + koff;
                float2 l0 = *(const float2*)xp;
                float2 l1 = *(const float2*)(xp + 8 * CDIM);
                float2 h0 = *(const float2*)(xp + 8);
                float2 h1 = *(const float2*)(xp + 8 * CDIM + 8);
                A[m][0] = cvt2(l0.x, l0.y);
                A[m][1] = cvt2(l1.x, l1.y);
                A[m][2] = cvt2(h0.x, h0.y);
                A[m][3] = cvt2(h1.x, h1.y);
            }
            const uint4* wk = (const uint4*)(wb + kc * KSTEP_U32) + lane;
#pragma unroll
            for (int jp = 0; jp < 4; jp++) {
                uint4 G = wk[jp * 32];
                mma16816(cacc[0][2 * jp],     A[0], G.x, G.y);
                mma16816(cacc[0][2 * jp + 1], A[0], G.z, G.w);
                mma16816(cacc[1][2 * jp],     A[1], G.x, G.y);
                mma16816(cacc[1][2 * jp + 1], A[1], G.z, G.w);
            }
        }
        __syncthreads();
        if (c + 2 < 16) load2(c + 2);
    }

    // ---- combine k-halves ----
    if (kh == 0) {
#pragma unroll
        for (int m = 0; m < 2; m++)
#pragma unroll
            for (int j = 0; j < 8; j++) {
                int row = wg * 32 + m * 16 + r;
                int nb = 8 * j + c0;
                *(float2*)&lsm[row * LSTR + nb]       = make_float2(cacc[m][j][0], cacc[m][j][1]);
                *(float2*)&lsm[(row + 8) * LSTR + nb] = make_float2(cacc[m][j][2], cacc[m][j][3]);
            }
    }
    __syncthreads();
    if (kh == 1) {
#pragma unroll
        for (int m = 0; m < 2; m++)
#pragma unroll
            for (int j = 0; j < 8; j++) {
                int row = wg * 32 + m * 16 + r;
                int nb = 8 * j + c0;
                float2 a = *(float2*)&lsm[row * LSTR + nb];
                float2 b = *(float2*)&lsm[(row + 8) * LSTR + nb];
                *(float2*)&lsm[row * LSTR + nb]       = make_float2(a.x + cacc[m][j][0], a.y + cacc[m][j][1]);
                *(float2*)&lsm[(row + 8) * LSTR + nb] = make_float2(b.x + cacc[m][j][2], b.y + cacc[m][j][3]);
            }
    }
    __syncthreads();

    // ---- per-token epilogue: top-10 candidates, S_rest, guard, probsums ----
    if (tid < TOKB) {
        float* row = lsm + tid * LSTR;

        float v0=-1e38f,v1=-1e38f,v2=-1e38f,v3=-1e38f,v4=-1e38f;
        float v5=-1e38f,v6=-1e38f,v7=-1e38f,v8=-1e38f,v9=-1e38f;
        int   i0=0,i1=0,i2=0,i3=0,i4=0,i5=0,i6=0,i7=0,i8=0,i9=0;
        for (int e = 0; e < EXPN; e++) {
            float l = row[e];
            if (l > v9) {
                v9 = l; i9 = e;
                if (v9 > v8) { float t=v8;v8=v9;v9=t; int u=i8;i8=i9;i9=u;
                if (v8 > v7) { t=v7;v7=v8;v8=t; u=i7;i7=i8;i8=u;
                if (v7 > v6) { t=v6;v6=v7;v7=t; u=i6;i6=i7;i7=u;
                if (v6 > v5) { t=v5;v5=v6;v6=t; u=i5;i5=i6;i6=u;
                if (v5 > v4) { t=v4;v4=v5;v5=t; u=i4;i4=i5;i5=u;
                if (v4 > v3) { t=v3;v3=v4;v4=t; u=i3;i3=i4;i4=u;
                if (v3 > v2) { t=v2;v2=v3;v3=t; u=i2;i2=i3;i3=u;
                if (v2 > v1) { t=v1;v1=v2;v2=t; u=i1;i1=i2;i2=u;
                if (v1 > v0) { t=v0;v0=v1;v1=t; u=i0;i0=i1;i1=u; } } } } } } } } }
            }
        }

        const int tok = blk * TOKB + tid;
        float m = v0;
        float ssum = 0.f;
        for (int e = 0; e < EXPN; e++) {
            float p = expf(row[e] - m);
            ssum += p;
            row[e] = p;
        }
        float ec = row[i0] + row[i1] + row[i2] + row[i3] + row[i4]
                 + row[i5] + row[i6] + row[i7] + row[i8] + row[i9];

        uint32_t ids0 = (uint32_t)i0 | ((uint32_t)i1 << 6) | ((uint32_t)i2 << 12)
                      | ((uint32_t)i3 << 18) | ((uint32_t)i4 << 24);
        uint32_t ids1 = (uint32_t)i5 | ((uint32_t)i6 << 6) | ((uint32_t)i7 << 12)
                      | ((uint32_t)i8 << 18) | ((uint32_t)i9 << 24);
        g_info[tok] = make_uint4(ids0, ids1,
                                 __float_as_uint(ssum - ec), __float_as_uint(m));

        if (v5 - v9 < GUARD) {
            int slot = atomicAdd(&g_fullcnt, 1);
            g_ffull[slot] = tok;
        }

        float inv = 1.0f / ssum;
        for (int jj = 0; jj < EXPN; jj++) {
            int e = (tid + jj) & (EXPN - 1);
            atomicAdd(&s_sums[e], row[e] * inv);
        }
    }
    __syncthreads();

    if (tid < EXPN) {
        int b = blk >> 5;
        atomicAdd(&g_sums[b * EXPN + tid], s_sums[tid]);
    }
}

// ---------------- refine: exact (R1-order) top-10 re-sort + weights + counts --------
__global__ void __launch_bounds__(320, 2)
refine_kernel(const float* __restrict__ x, const float* __restrict__ w,
              float* __restrict__ out) {
    extern __shared__ float sf[];
    float* ws = sf + RWS;    // 64 x 130
    float* xs = sf + RXS;    // 32 x 130
    float* lg = sf + RLG;    // 320
    __shared__ float scnt[EXPN];

    const int tid  = threadIdx.x;
    const int tok0 = blockIdx.x * 32;
    const int tl   = tid / 10;        // token slot 0..31
    const int cand = tid - tl * 10;   // candidate slot 0..9

    if (tid < EXPN) scnt[tid] = 0.f;

    uint4 inf = g_info[tok0 + (tl < 32 ? tl : 31)];
    int eid = (cand < 5) ? ((inf.x >> (6 * cand)) & 63)
                         : ((inf.y >> (6 * (cand - 5))) & 63);

    float accE = 0.f, accO = 0.f;
    for (int ch = 0; ch < 16; ch++) {
        __syncthreads();
        for (int i = tid; i < 64 * 32; i += 320) {
            int row = i >> 5, q = i & 31;
            float4 v = *(const float4*)(w + (size_t)row * CDIM + ch * 128 + q * 4);
            float* d = &ws[row * 130 + q * 4];
            d[0] = v.x; d[1] = v.y; d[2] = v.z; d[3] = v.w;
        }
        for (int i = tid; i < 32 * 32; i += 320) {
            int row = i >> 5, q = i & 31;
            float4 v = *(const float4*)(x + (size_t)(tok0 + row) * CDIM + ch * 128 + q * 4);
            float* d = &xs[row * 130 + q * 4];
            d[0] = v.x; d[1] = v.y; d[2] = v.z; d[3] = v.w;
        }
        __syncthreads();
        const float* xr = &xs[(tl < 32 ? tl : 31) * 130];
        const float* wr = &ws[eid * 130];
#pragma unroll 8
        for (int kk = 0; kk < 128; kk += 2) {
            float2 xv = *(const float2*)(xr + kk);
            float2 wv = *(const float2*)(wr + kk);
            accE = fmaf(xv.x, wv.x, accE);
            accO = fmaf(xv.y, wv.y, accO);
        }
    }
    if (tid < 320) lg[tid] = accE + accO;
    __syncthreads();

    if (tid < 32) {
        const int tok = tok0 + tid;
        uint4 nf = g_info[tok];
        float v[10]; int id[10];
#pragma unroll
        for (int j = 0; j < 10; j++) {
            id[j] = (j < 5) ? ((nf.x >> (6 * j)) & 63) : ((nf.y >> (6 * (j - 5))) & 63);
            v[j] = lg[tid * 10 + j];
        }
        // insertion sort desc by exact value; ties -> lower expert index first
#pragma unroll
        for (int i = 1; i < 10; i++) {
            float kv = v[i]; int ki = id[i];
            int j = i - 1;
            while (j >= 0 && (v[j] < kv || (v[j] == kv && id[j] > ki))) {
                v[j + 1] = v[j]; id[j + 1] = id[j];
                j--;
            }
            v[j + 1] = kv; id[j + 1] = ki;
        }
        float m  = __uint_as_float(nf.w);
        float D  = __uint_as_float(nf.z);   // S_rest
        float ex[10];
#pragma unroll
        for (int j = 0; j < 10; j++) { ex[j] = expf(v[j] - m); D += ex[j]; }
        float invD = 1.0f / D;

        float* out_idx = out;
        float* out_wgt = out + (size_t)BT * TOPK;
#pragma unroll
        for (int j = 0; j < TOPK; j++) {
            out_idx[(size_t)tok * TOPK + j] = (float)id[j];
            out_wgt[(size_t)tok * TOPK + j] = ex[j] * invD;
            atomicAdd(&scnt[id[j]], 1.0f);
        }
    }
    __syncthreads();
    if (tid < EXPN) atomicAdd(&g_cnts[(tok0 >> 12) * EXPN + tid], scnt[tid]);
}

// ---------------- full fixup (guarded tokens) + aux ----------------
__global__ void __launch_bounds__(256, 1)
fix_kernel(const float* __restrict__ x, const float* __restrict__ w,
           float* __restrict__ out) {
    __shared__ float ws[EXPN * 129];
    __shared__ float lg[4][EXPN];
    __shared__ float red[256];
    const int tid = threadIdx.x;
    const int tg  = tid >> 6;
    const int e   = tid & 63;
    const int nflag = g_fullcnt;

    for (int base = blockIdx.x * 4; base < nflag; base += gridDim.x * 4) {
        const int fi  = base + tg;
        const int tok = g_ffull[fi < nflag ? fi : (nflag - 1)];

        float accE = 0.f, accO = 0.f;
        for (int ch = 0; ch < 16; ch++) {
            __syncthreads();
            for (int i = tid; i < EXPN * 32; i += 256) {
                int row = i >> 5, q4 = i & 31;
                float4 v = *(const float4*)(w + (size_t)row * CDIM + ch * 128 + q4 * 4);
                float* d = &ws[row * 129 + q4 * 4];
                d[0] = v.x; d[1] = v.y; d[2] = v.z; d[3] = v.w;
            }
            __syncthreads();
            const float* xp = x + (size_t)tok * CDIM + ch * 128;
            const float* wr = &ws[e * 129];
#pragma unroll 8
            for (int kk = 0; kk < 128; kk += 2) {
                float2 xv = *(const float2*)(xp + kk);
                accE = fmaf(xv.x, wr[kk],     accE);
                accO = fmaf(xv.y, wr[kk + 1], accO);
            }
        }
        lg[tg][e] = accE + accO;
        __syncthreads();

        if (tid < 4 && base + tid < nflag) {
            const int t2 = g_ffull[base + tid];
            const float* row = lg[tid];
            float v0=-1e38f,v1=-1e38f,v2=-1e38f,v3=-1e38f,v4=-1e38f,v5=-1e38f;
            int   i0=0,i1=0,i2=0,i3=0,i4=0,i5=0;
            for (int k = 0; k < EXPN; k++) {
                float l = row[k];
                if (l > v5) {
                    v5 = l; i5 = k;
                    if (v5 > v4) { float t=v4;v4=v5;v5=t; int u=i4;i4=i5;i5=u; }
                    if (v4 > v3) { float t=v3;v3=v4;v4=t; int u=i3;i3=i4;i4=u; }
                    if (v3 > v2) { float t=v2;v2=v3;v3=t; int u=i2;i2=i3;i3=u; }
                    if (v2 > v1) { float t=v1;v1=v2;v2=t; int u=i1;i1=i2;i2=u; }
                    if (v1 > v0) { float t=v0;v0=v1;v1=t; int u=i0;i0=i1;i1=u; }
                }
            }
            float m = v0;
            float ssum = 0.f;
            for (int k = 0; k < EXPN; k++) ssum += expf(row[k] - m);
            float inv = 1.0f / ssum;
            float* out_idx = out;
            float* out_wgt = out + (size_t)BT * TOPK;
            const size_t g = (size_t)t2;
            out_idx[g * TOPK + 0] = (float)i0;
            out_idx[g * TOPK + 1] = (float)i1;
            out_idx[g * TOPK + 2] = (float)i2;
            out_idx[g * TOPK + 3] = (float)i3;
            out_idx[g * TOPK + 4] = (float)i4;
            out_idx[g * TOPK + 5] = (float)i5;
            out_wgt[g * TOPK + 0] = expf(v0 - m) * inv;
            out_wgt[g * TOPK + 1] = expf(v1 - m) * inv;
            out_wgt[g * TOPK + 2] = expf(v2 - m) * inv;
            out_wgt[g * TOPK + 3] = expf(v3 - m) * inv;
            out_wgt[g * TOPK + 4] = expf(v4 - m) * inv;
            out_wgt[g * TOPK + 5] = expf(v5 - m) * inv;
        }
        __syncthreads();
    }

    if (blockIdx.x == 0) {
        red[tid] = g_cnts[tid] * g_sums[tid];
        __syncthreads();
#pragma unroll
        for (int s2 = 128; s2 > 0; s2 >>= 1) {
            if (tid < s2) red[tid] += red[tid + s2];
            __syncthreads();
        }
        if (tid == 0) {
            const float scale = (float)(0.001 * 64.0 / ((double)4 * 4096.0 * 6.0 * 4096.0));
            out[(size_t)BT * 12] = red[0] * scale;
        }
    }
}

extern "C" void kernel_launch(void* const* d_in, const int* in_sizes, int n_in,
                              void* d_out, int out_size) {
    const float* x = (const float*)d_in[0];
    const float* w = (const float*)d_in[1];
    float* out = (float*)d_out;

    cudaFuncSetAttribute(gate_kernel, cudaFuncAttributeMaxDynamicSharedMemorySize, SMEM_BYTES);
    cudaFuncSetAttribute(refine_kernel, cudaFuncAttributeMaxDynamicSharedMemorySize, REFINE_SMEM);

    prep_kernel<<<128, 256>>>(w);
    gate_kernel<<<BT / TOKB, NTHR, SMEM_BYTES>>>(x);
    refine_kernel<<<BT / 32, 320, REFINE_SMEM>>>(x, w, out);
    fix_kernel<<<64, 256>>>(x, w, out);
}

// round 15
// speedup vs baseline: 1.1283x; 1.1283x over previous
#include <cuda_runtime.h>
#include <cuda_bf16.h>
#include <cstdint>

#define NTHR 256
#define TOKB 128
#define EXPN 64
#define CDIM 2048
#define BT   16384
#define BDIM 4
#define TOPK 6
#define KSTEP_U32 512            // u32 per kstep packed W (4 jp * 32 lanes * 4)
#define CHUNK_U32 (4*KSTEP_U32)  // 2048 u32 = 8KB (4 ksteps)
#define LSTR 66
#define GUARD 0.012f
#define SMEM_BYTES (4*CHUNK_U32*4 + TOKB*LSTR*4)   // 66560

// refine smem layout (floats): ws 64x132, xs 64x132, lg 640
#define RWS  0
#define RXS  (64*132)
#define RLG  (2*64*132)
#define REFINE_SMEM ((2*64*132 + 640) * 4)   // 70144 B

__device__ float g_sums[BDIM * EXPN];
__device__ float g_cnts[BDIM * EXPN];
__device__ int   g_fullcnt;
__device__ int   g_ffull[BT];
__device__ uint4 g_info[BT];               // {ids0, ids1, S_rest, m}
__device__ uint32_t wsg[128 * KSTEP_U32];  // 256 KB packed 1-plane bf16 W fragments

static __device__ __forceinline__ void cp16(void* smem_ptr, const void* gptr) {
    unsigned saddr = (unsigned)__cvta_generic_to_shared(smem_ptr);
    asm volatile("cp.async.cg.shared.global [%0], [%1], 16;\n" :: "r"(saddr), "l"(gptr));
}
#define CP_COMMIT() asm volatile("cp.async.commit_group;\n" ::: "memory")

static __device__ __forceinline__ void mma16816(float* c, const uint32_t* a,
                                                uint32_t b0, uint32_t b1) {
    asm volatile("mma.sync.aligned.m16n8k16.row.col.f32.bf16.bf16.f32 "
        "{%0,%1,%2,%3}, {%4,%5,%6,%7}, {%8,%9}, {%0,%1,%2,%3};"
        : "+f"(c[0]), "+f"(c[1]), "+f"(c[2]), "+f"(c[3])
        : "r"(a[0]), "r"(a[1]), "r"(a[2]), "r"(a[3]), "r"(b0), "r"(b1));
}

static __device__ __forceinline__ uint32_t cvt2(float f0, float f1) {
    __nv_bfloat162 b = __floats2bfloat162_rn(f0, f1);
    return *(uint32_t*)&b;
}

// ---------------- W prep: single bf16 plane, B-fragment lane order ----------------
__global__ void prep_kernel(const float* __restrict__ w) {
    int id = blockIdx.x * 256 + threadIdx.x;
    if (id < BDIM * EXPN) { g_sums[id] = 0.f; g_cnts[id] = 0.f; }
    if (id == 0) g_fullcnt = 0;
    int s = id >> 8;
    int j = (id >> 5) & 7;
    int l = id & 31;
    int n  = 8 * j + (l >> 2);
    int k0 = s * 16 + (l & 3) * 2;
    const float* wr = w + (size_t)n * CDIM + k0;
    float2 flo = *(const float2*)wr;
    float2 fhi = *(const float2*)(wr + 8);
    uint32_t b0 = cvt2(flo.x, flo.y);
    uint32_t b1 = cvt2(fhi.x, fhi.y);
    uint32_t base = (uint32_t)(((s * 4 + (j >> 1)) * 32 + l) * 4 + (j & 1) * 2);
    wsg[base]     = b0;
    wsg[base + 1] = b1;
}

// ---------------- gate: 1-term bf16 HMMA, emits top-10 candidates ----------------
__global__ void __launch_bounds__(NTHR, 1)
gate_kernel(const float* __restrict__ x) {
    extern __shared__ char smem[];
    uint32_t* wbuf = (uint32_t*)smem;
    float* lsm = (float*)(smem + 4 * CHUNK_U32 * 4);
    __shared__ float s_sums[EXPN];

    const int tid  = threadIdx.x;
    const int wid  = tid >> 5;
    const int lane = tid & 31;
    const int blk  = blockIdx.x;
    const int wg   = wid & 3;
    const int kh   = wid >> 2;

    if (tid < EXPN) s_sums[tid] = 0.f;

    const int r  = lane >> 2;
    const int c0 = (lane & 3) * 2;
    const float* xr0 = x + ((size_t)blk * TOKB + wg * 32 + r) * CDIM + kh * 1024;
    const float* xr1 = xr0 + (size_t)16 * CDIM;

    float cacc[2][8][4];
#pragma unroll
    for (int m = 0; m < 2; m++)
#pragma unroll
        for (int j = 0; j < 8; j++)
#pragma unroll
            for (int q = 0; q < 4; q++) cacc[m][j][q] = 0.f;

    auto load2 = [&](int c) {
        int par = c & 1;
        const uint4* s0 = (const uint4*)(wsg + (size_t)c * CHUNK_U32);
        const uint4* s1 = (const uint4*)(wsg + (size_t)(16 + c) * CHUNK_U32);
        uint4* d0 = (uint4*)(wbuf + par * CHUNK_U32);
        uint4* d1 = (uint4*)(wbuf + (2 + par) * CHUNK_U32);
#pragma unroll
        for (int i = 0; i < 2; i++) cp16(d0 + tid + i * NTHR, s0 + tid + i * NTHR);
#pragma unroll
        for (int i = 0; i < 2; i++) cp16(d1 + tid + i * NTHR, s1 + tid + i * NTHR);
        CP_COMMIT();
    };

    load2(0);
    load2(1);

    for (int c = 0; c < 16; c++) {
        if (c + 1 < 16) asm volatile("cp.async.wait_group 1;\n" ::: "memory");
        else            asm volatile("cp.async.wait_group 0;\n" ::: "memory");
        __syncthreads();

        const uint32_t* wb = wbuf + (kh * 2 + (c & 1)) * CHUNK_U32;

#pragma unroll
        for (int kc = 0; kc < 4; kc++) {
            const int koff = (c * 4 + kc) * 16 + c0;
            uint32_t A[2][4];
#pragma unroll
            for (int m = 0; m < 2; m++) {
                const float* xp = (m == 0 ? xr0 : xr1) + koff;
                float2 l0 = *(const float2*)xp;
                float2 l1 = *(const float2*)(xp + 8 * CDIM);
                float2 h0 = *(const float2*)(xp + 8);
                float2 h1 = *(const float2*)(xp + 8 * CDIM + 8);
                A[m][0] = cvt2(l0.x, l0.y);
                A[m][1] = cvt2(l1.x, l1.y);
                A[m][2] = cvt2(h0.x, h0.y);
                A[m][3] = cvt2(h1.x, h1.y);
            }
            const uint4* wk = (const uint4*)(wb + kc * KSTEP_U32) + lane;
#pragma unroll
            for (int jp = 0; jp < 4; jp++) {
                uint4 G = wk[jp * 32];
                mma16816(cacc[0][2 * jp],     A[0], G.x, G.y);
                mma16816(cacc[0][2 * jp + 1], A[0], G.z, G.w);
                mma16816(cacc[1][2 * jp],     A[1], G.x, G.y);
                mma16816(cacc[1][2 * jp + 1], A[1], G.z, G.w);
            }
        }
        __syncthreads();
        if (c + 2 < 16) load2(c + 2);
    }

    if (kh == 0) {
#pragma unroll
        for (int m = 0; m < 2; m++)
#pragma unroll
            for (int j = 0; j < 8; j++) {
                int row = wg * 32 + m * 16 + r;
                int nb = 8 * j + c0;
                *(float2*)&lsm[row * LSTR + nb]       = make_float2(cacc[m][j][0], cacc[m][j][1]);
                *(float2*)&lsm[(row + 8) * LSTR + nb] = make_float2(cacc[m][j][2], cacc[m][j][3]);
            }
    }
    __syncthreads();
    if (kh == 1) {
#pragma unroll
        for (int m = 0; m < 2; m++)
#pragma unroll
            for (int j = 0; j < 8; j++) {
                int row = wg * 32 + m * 16 + r;
                int nb = 8 * j + c0;
                float2 a = *(float2*)&lsm[row * LSTR + nb];
                float2 b = *(float2*)&lsm[(row + 8) * LSTR + nb];
                *(float2*)&lsm[row * LSTR + nb]       = make_float2(a.x + cacc[m][j][0], a.y + cacc[m][j][1]);
                *(float2*)&lsm[(row + 8) * LSTR + nb] = make_float2(b.x + cacc[m][j][2], b.y + cacc[m][j][3]);
            }
    }
    __syncthreads();

    if (tid < TOKB) {
        float* row = lsm + tid * LSTR;

        float v0=-1e38f,v1=-1e38f,v2=-1e38f,v3=-1e38f,v4=-1e38f;
        float v5=-1e38f,v6=-1e38f,v7=-1e38f,v8=-1e38f,v9=-1e38f;
        int   i0=0,i1=0,i2=0,i3=0,i4=0,i5=0,i6=0,i7=0,i8=0,i9=0;
        for (int e = 0; e < EXPN; e++) {
            float l = row[e];
            if (l > v9) {
                v9 = l; i9 = e;
                if (v9 > v8) { float t=v8;v8=v9;v9=t; int u=i8;i8=i9;i9=u;
                if (v8 > v7) { t=v7;v7=v8;v8=t; u=i7;i7=i8;i8=u;
                if (v7 > v6) { t=v6;v6=v7;v7=t; u=i6;i6=i7;i7=u;
                if (v6 > v5) { t=v5;v5=v6;v6=t; u=i5;i5=i6;i6=u;
                if (v5 > v4) { t=v4;v4=v5;v5=t; u=i4;i4=i5;i5=u;
                if (v4 > v3) { t=v3;v3=v4;v4=t; u=i3;i3=i4;i4=u;
                if (v3 > v2) { t=v2;v2=v3;v3=t; u=i2;i2=i3;i3=u;
                if (v2 > v1) { t=v1;v1=v2;v2=t; u=i1;i1=i2;i2=u;
                if (v1 > v0) { t=v0;v0=v1;v1=t; u=i0;i0=i1;i1=u; } } } } } } } } }
            }
        }

        const int tok = blk * TOKB + tid;
        float m = v0;
        float ssum = 0.f;
        for (int e = 0; e < EXPN; e++) {
            float p = expf(row[e] - m);
            ssum += p;
            row[e] = p;
        }
        float ec = row[i0] + row[i1] + row[i2] + row[i3] + row[i4]
                 + row[i5] + row[i6] + row[i7] + row[i8] + row[i9];

        uint32_t ids0 = (uint32_t)i0 | ((uint32_t)i1 << 6) | ((uint32_t)i2 << 12)
                      | ((uint32_t)i3 << 18) | ((uint32_t)i4 << 24);
        uint32_t ids1 = (uint32_t)i5 | ((uint32_t)i6 << 6) | ((uint32_t)i7 << 12)
                      | ((uint32_t)i8 << 18) | ((uint32_t)i9 << 24);
        g_info[tok] = make_uint4(ids0, ids1,
                                 __float_as_uint(ssum - ec), __float_as_uint(m));

        if (v5 - v9 < GUARD) {
            int slot = atomicAdd(&g_fullcnt, 1);
            g_ffull[slot] = tok;
        }

        float inv = 1.0f / ssum;
        for (int jj = 0; jj < EXPN; jj++) {
            int e = (tid + jj) & (EXPN - 1);
            atomicAdd(&s_sums[e], row[e] * inv);
        }
    }
    __syncthreads();

    if (tid < EXPN) {
        int b = blk >> 5;
        atomicAdd(&g_sums[b * EXPN + tid], s_sums[tid]);
    }
}

// ---------------- refine: exact (R1-order) top-10 re-sort, 64 tokens/block ----------
__global__ void __launch_bounds__(640, 2)
refine_kernel(const float* __restrict__ x, const float* __restrict__ w,
              float* __restrict__ out) {
    extern __shared__ float sf[];
    float* ws = sf + RWS;    // 64 x 132
    float* xs = sf + RXS;    // 64 x 132
    float* lg = sf + RLG;    // 640
    __shared__ float scnt[EXPN];

    const int tid  = threadIdx.x;
    const int tok0 = blockIdx.x * 64;
    const int tl   = tid / 10;        // token slot 0..63
    const int cand = tid - tl * 10;   // candidate slot 0..9

    if (tid < EXPN) scnt[tid] = 0.f;

    uint4 inf = g_info[tok0 + tl];
    int eid = (cand < 5) ? ((inf.x >> (6 * cand)) & 63)
                         : ((inf.y >> (6 * (cand - 5))) & 63);

    float accE = 0.f, accO = 0.f;
    for (int ch = 0; ch < 16; ch++) {
        __syncthreads();
#pragma unroll
        for (int it = 0; it < 4; it++) {
            int i = tid + it * 640;
            if (i < 2048) {
                int row = i >> 5, q = i & 31;
                *(float4*)&ws[row * 132 + q * 4] =
                    *(const float4*)(w + (size_t)row * CDIM + ch * 128 + q * 4);
                *(float4*)&xs[row * 132 + q * 4] =
                    *(const float4*)(x + (size_t)(tok0 + row) * CDIM + ch * 128 + q * 4);
            }
        }
        __syncthreads();
        const float4* xr = (const float4*)&xs[tl * 132];
        const float4* wr = (const float4*)&ws[eid * 132];
#pragma unroll 8
        for (int kk4 = 0; kk4 < 32; kk4++) {
            float4 xv = xr[kk4];
            float4 wv = wr[kk4];
            accE = fmaf(xv.x, wv.x, accE);
            accO = fmaf(xv.y, wv.y, accO);
            accE = fmaf(xv.z, wv.z, accE);
            accO = fmaf(xv.w, wv.w, accO);
        }
    }
    lg[tid] = accE + accO;
    __syncthreads();

    if (tid < 64) {
        const int tok = tok0 + tid;
        uint4 nf = g_info[tok];
        float v[10]; int id[10];
#pragma unroll
        for (int j = 0; j < 10; j++) {
            id[j] = (j < 5) ? ((nf.x >> (6 * j)) & 63) : ((nf.y >> (6 * (j - 5))) & 63);
            v[j] = lg[tid * 10 + j];
        }
        // odd-even transposition sorting network: desc by value, ties -> lower id first
#pragma unroll
        for (int p = 0; p < 10; p++) {
#pragma unroll
            for (int i = (p & 1); i < 9; i += 2) {
                bool sw = (v[i] < v[i+1]) || (v[i] == v[i+1] && id[i] > id[i+1]);
                float tv = sw ? v[i]  : v[i+1];
                int   ti = sw ? id[i] : id[i+1];
                v[i]  = sw ? v[i+1]  : v[i];
                id[i] = sw ? id[i+1] : id[i];
                v[i+1]  = tv;
                id[i+1] = ti;
            }
        }
        float m  = __uint_as_float(nf.w);
        float D  = __uint_as_float(nf.z);   // S_rest
        float ex[10];
#pragma unroll
        for (int j = 0; j < 10; j++) { ex[j] = expf(v[j] - m); D += ex[j]; }
        float invD = 1.0f / D;

        float* out_idx = out;
        float* out_wgt = out + (size_t)BT * TOPK;
#pragma unroll
        for (int j = 0; j < TOPK; j++) {
            out_idx[(size_t)tok * TOPK + j] = (float)id[j];
            out_wgt[(size_t)tok * TOPK + j] = ex[j] * invD;
            atomicAdd(&scnt[id[j]], 1.0f);
        }
    }
    __syncthreads();
    if (tid < EXPN) atomicAdd(&g_cnts[(tok0 >> 12) * EXPN + tid], scnt[tid]);
}

// ---------------- full fixup (guarded tokens) + aux ----------------
__global__ void __launch_bounds__(256, 1)
fix_kernel(const float* __restrict__ x, const float* __restrict__ w,
           float* __restrict__ out) {
    __shared__ float ws[EXPN * 129];
    __shared__ float lg[4][EXPN];
    __shared__ float red[256];
    const int tid = threadIdx.x;
    const int tg  = tid >> 6;
    const int e   = tid & 63;
    const int nflag = g_fullcnt;

    for (int base = blockIdx.x * 4; base < nflag; base += gridDim.x * 4) {
        const int fi  = base + tg;
        const int tok = g_ffull[fi < nflag ? fi : (nflag - 1)];

        float accE = 0.f, accO = 0.f;
        for (int ch = 0; ch < 16; ch++) {
            __syncthreads();
            for (int i = tid; i < EXPN * 32; i += 256) {
                int row = i >> 5, q4 = i & 31;
                *(float4*)&ws[row * 129 + q4 * 4] = make_float4(0.f, 0.f, 0.f, 0.f);
                float4 v = *(const float4*)(w + (size_t)row * CDIM + ch * 128 + q4 * 4);
                float* d = &ws[row * 129 + q4 * 4];
                d[0] = v.x; d[1] = v.y; d[2] = v.z; d[3] = v.w;
            }
            __syncthreads();
            const float* xp = x + (size_t)tok * CDIM + ch * 128;
            const float* wr = &ws[e * 129];
#pragma unroll 8
            for (int kk = 0; kk < 128; kk += 2) {
                float2 xv = *(const float2*)(xp + kk);
                accE = fmaf(xv.x, wr[kk],     accE);
                accO = fmaf(xv.y, wr[kk + 1], accO);
            }
        }
        lg[tg][e] = accE + accO;
        __syncthreads();

        if (tid < 4 && base + tid < nflag) {
            const int t2 = g_ffull[base + tid];
            const float* row = lg[tid];
            float v0=-1e38f,v1=-1e38f,v2=-1e38f,v3=-1e38f,v4=-1e38f,v5=-1e38f;
            int   i0=0,i1=0,i2=0,i3=0,i4=0,i5=0;
            for (int k = 0; k < EXPN; k++) {
                float l = row[k];
                if (l > v5) {
                    v5 = l; i5 = k;
                    if (v5 > v4) { float t=v4;v4=v5;v5=t; int u=i4;i4=i5;i5=u; }
                    if (v4 > v3) { float t=v3;v3=v4;v4=t; int u=i3;i3=i4;i4=u; }
                    if (v3 > v2) { float t=v2;v2=v3;v3=t; int u=i2;i2=i3;i3=u; }
                    if (v2 > v1) { float t=v1;v1=v2;v2=t; int u=i1;i1=i2;i2=u; }
                    if (v1 > v0) { float t=v0;v0=v1;v1=t; int u=i0;i0=i1;i1=u; }
                }
            }
            float m = v0;
            float ssum = 0.f;
            for (int k = 0; k < EXPN; k++) ssum += expf(row[k] - m);
            float inv = 1.0f / ssum;
            float* out_idx = out;
            float* out_wgt = out + (size_t)BT * TOPK;
            const size_t g = (size_t)t2;
            out_idx[g * TOPK + 0] = (float)i0;
            out_idx[g * TOPK + 1] = (float)i1;
            out_idx[g * TOPK + 2] = (float)i2;
            out_idx[g * TOPK + 3] = (float)i3;
            out_idx[g * TOPK + 4] = (float)i4;
            out_idx[g * TOPK + 5] = (float)i5;
            out_wgt[g * TOPK + 0] = expf(v0 - m) * inv;
            out_wgt[g * TOPK + 1] = expf(v1 - m) * inv;
            out_wgt[g * TOPK + 2] = expf(v2 - m) * inv;
            out_wgt[g * TOPK + 3] = expf(v3 - m) * inv;
            out_wgt[g * TOPK + 4] = expf(v4 - m) * inv;
            out_wgt[g * TOPK + 5] = expf(v5 - m) * inv;
        }
        __syncthreads();
    }

    if (blockIdx.x == 0) {
        red[tid] = g_cnts[tid] * g_sums[tid];
        __syncthreads();
#pragma unroll
        for (int s2 = 128; s2 > 0; s2 >>= 1) {
            if (tid < s2) red[tid] += red[tid + s2];
            __syncthreads();
        }
        if (tid == 0) {
            const float scale = (float)(0.001 * 64.0 / ((double)4 * 4096.0 * 6.0 * 4096.0));
            out[(size_t)BT * 12] = red[0] * scale;
        }
    }
}

extern "C" void kernel_launch(void* const* d_in, const int* in_sizes, int n_in,
                              void* d_out, int out_size) {
    const float* x = (const float*)d_in[0];
    const float* w = (const float*)d_in[1];
    float* out = (float*)d_out;

    cudaFuncSetAttribute(gate_kernel, cudaFuncAttributeMaxDynamicSharedMemorySize, SMEM_BYTES);
    cudaFuncSetAttribute(refine_kernel, cudaFuncAttributeMaxDynamicSharedMemorySize, REFINE_SMEM);

    prep_kernel<<<128, 256>>>(w);
    gate_kernel<<<BT / TOKB, NTHR, SMEM_BYTES>>>(x);
    refine_kernel<<<BT / 64, 640, REFINE_SMEM>>>(x, w, out);
    fix_kernel<<<256, 256>>>(x, w, out);
}